// round 17
// baseline (speedup 1.0000x reference)
#include <cuda_runtime.h>
#include <cuda_fp16.h>
#include <math.h>
#include <stdint.h>

#define T_TOK 8192
#define D_DIM 1024
#define H_DIM 4096
#define E_NUM 8
#define OUT_ELEMS (T_TOK * D_DIM)

// ---------------- scratch ----------------
__device__ __half g_x16[(size_t)T_TOK * D_DIM];            // 16 MiB
__device__ __half g_w1h[(size_t)E_NUM * D_DIM * H_DIM];    // 64 MiB
__device__ __half g_w2h[(size_t)E_NUM * H_DIM * D_DIM];    // 64 MiB
__device__ __half g_mid[(size_t)2 * T_TOK * H_DIM];        // 128 MiB
__device__ float  g_out2[(size_t)2 * T_TOK * D_DIM];       // 64 MiB
__device__ int   g_cnt[E_NUM];
__device__ int   g_tok[E_NUM * T_TOK];
__device__ int   g_slot[E_NUM * T_TOK];
__device__ float g_wt[E_NUM * T_TOK];

__device__ __forceinline__ uint32_t smem_u32(const void* p) {
    uint32_t a;
    asm("{ .reg .u64 t; cvta.to.shared.u64 t, %1; cvt.u32.u64 %0, t; }" : "=r"(a) : "l"(p));
    return a;
}
__device__ __forceinline__ void cp16(uint32_t dst, const void* src) {
    asm volatile("cp.async.cg.shared.global [%0], [%1], 16;" :: "r"(dst), "l"(src) : "memory");
}
__device__ __forceinline__ void cp_commit() {
    asm volatile("cp.async.commit_group;" ::: "memory");
}
template<int N>
__device__ __forceinline__ void cp_wait() {
    asm volatile("cp.async.wait_group %0;" :: "n"(N) : "memory");
}
__device__ __forceinline__ void ldsm_x4(uint32_t* r, uint32_t addr) {
    asm volatile("ldmatrix.sync.aligned.m8n8.x4.shared.b16 {%0,%1,%2,%3}, [%4];"
                 : "=r"(r[0]), "=r"(r[1]), "=r"(r[2]), "=r"(r[3]) : "r"(addr));
}
__device__ __forceinline__ void ldsm_x4_t(uint32_t* r, uint32_t addr) {
    asm volatile("ldmatrix.sync.aligned.m8n8.x4.trans.shared.b16 {%0,%1,%2,%3}, [%4];"
                 : "=r"(r[0]), "=r"(r[1]), "=r"(r[2]), "=r"(r[3]) : "r"(addr));
}
__device__ __forceinline__ void mma16816(float* c, const uint32_t* a, const uint32_t* b) {
    asm volatile(
        "mma.sync.aligned.m16n8k16.row.col.f32.f16.f16.f32 "
        "{%0,%1,%2,%3}, {%4,%5,%6,%7}, {%8,%9}, {%0,%1,%2,%3};"
        : "+f"(c[0]), "+f"(c[1]), "+f"(c[2]), "+f"(c[3])
        : "r"(a[0]), "r"(a[1]), "r"(a[2]), "r"(a[3]), "r"(b[0]), "r"(b[1]));
}

// ---------------- small kernels ----------------
// combine also re-zeros g_cnt for the next graph replay (globals are
// zero-initialized at module load, so the first call sees zeros too).
__global__ __launch_bounds__(256) void combine_kernel(float4* __restrict__ out) {
    int i = blockIdx.x * blockDim.x + threadIdx.x;
    if (i < E_NUM) g_cnt[i] = 0;
    if (i >= OUT_ELEMS / 4) return;
    int t = i / (D_DIM / 4);
    int r = i % (D_DIM / 4);
    const float4* a = (const float4*)g_out2 + (size_t)(2 * t) * (D_DIM / 4) + r;
    const float4* b = (const float4*)g_out2 + (size_t)(2 * t + 1) * (D_DIM / 4) + r;
    float4 va = *a, vb = *b;
    out[i] = make_float4(va.x + vb.x, va.y + vb.y, va.z + vb.z, va.w + vb.w);
}

// ---------------- fused preamble: router + x convert + both weight converts --
#define RB 1024
#define NW8 (E_NUM * D_DIM * H_DIM / 8)
#define CONV_BLOCKS (2 * NW8 / 256)
#define PRE_GRID (RB + CONV_BLOCKS)

__global__ __launch_bounds__(256) void preamble_kernel(
    const float* __restrict__ x, const float* __restrict__ gw,
    const float* __restrict__ gb, float* __restrict__ logits_out,
    const float4* __restrict__ w1f, const float4* __restrict__ w2f) {
    int b = blockIdx.x;
    if (b >= RB) {
        int idx = (b - RB) * 256 + threadIdx.x;
        const float4* src; uint4* dst; int j;
        if (idx < NW8) { j = idx;        src = w1f; dst = (uint4*)g_w1h; }
        else           { j = idx - NW8;  src = w2f; dst = (uint4*)g_w2h; }
        float4 v0 = src[2 * j], v1 = src[2 * j + 1];
        __half2 h0 = __floats2half2_rn(v0.x, v0.y);
        __half2 h1 = __floats2half2_rn(v0.z, v0.w);
        __half2 h2 = __floats2half2_rn(v1.x, v1.y);
        __half2 h3 = __floats2half2_rn(v1.z, v1.w);
        dst[j] = make_uint4(*(uint32_t*)&h0, *(uint32_t*)&h1,
                            *(uint32_t*)&h2, *(uint32_t*)&h3);
        return;
    }
    int warp = b * 8 + (threadIdx.x >> 5);
    int lane = threadIdx.x & 31;
    int t = warp;

    float acc[E_NUM];
#pragma unroll
    for (int e = 0; e < E_NUM; e++) acc[e] = 0.f;
    const float* xr = x + (size_t)t * D_DIM;
    __half* xo = g_x16 + (size_t)t * D_DIM;
    for (int d = lane; d < D_DIM; d += 32) {
        float xv = xr[d];
        xo[d] = __float2half_rn(xv);
        const float4* g4 = (const float4*)(gw + (size_t)d * E_NUM);
        float4 a = g4[0], bb = g4[1];
        acc[0] += xv * a.x;  acc[1] += xv * a.y;  acc[2] += xv * a.z;  acc[3] += xv * a.w;
        acc[4] += xv * bb.x; acc[5] += xv * bb.y; acc[6] += xv * bb.z; acc[7] += xv * bb.w;
    }
#pragma unroll
    for (int e = 0; e < E_NUM; e++)
#pragma unroll
        for (int off = 16; off; off >>= 1)
            acc[e] += __shfl_xor_sync(0xffffffffu, acc[e], off);

    if (lane == 0) {
        float l[E_NUM];
#pragma unroll
        for (int e = 0; e < E_NUM; e++) {
            l[e] = acc[e] + gb[e];
            logits_out[t * E_NUM + e] = l[e];
        }
        float m = l[0];
#pragma unroll
        for (int e = 1; e < E_NUM; e++) m = fmaxf(m, l[e]);
        float p[E_NUM], s = 0.f;
#pragma unroll
        for (int e = 0; e < E_NUM; e++) { p[e] = expf(l[e] - m); s += p[e]; }
#pragma unroll
        for (int e = 0; e < E_NUM; e++) p[e] = p[e] / s;
        int e0 = 0;
#pragma unroll
        for (int e = 1; e < E_NUM; e++) if (p[e] > p[e0]) e0 = e;
        int e1 = (e0 == 0) ? 1 : 0;
#pragma unroll
        for (int e = 0; e < E_NUM; e++)
            if (e != e0 && p[e] > p[e1]) e1 = e;
        float denom = p[e0] + p[e1];

        int pos0 = atomicAdd(&g_cnt[e0], 1);
        g_tok[e0 * T_TOK + pos0]  = t;
        g_slot[e0 * T_TOK + pos0] = 2 * t;
        g_wt[e0 * T_TOK + pos0]   = p[e0] / denom;
        int pos1 = atomicAdd(&g_cnt[e1], 1);
        g_tok[e1 * T_TOK + pos1]  = t;
        g_slot[e1 * T_TOK + pos1] = 2 * t + 1;
        g_wt[e1 * T_TOK + pos1]   = p[e1] / denom;
    }
}

// -- grouped GEMM: 128x128 tile, 4 warps (warp tile 64x64), 128 threads,
//    5-buffer ring, 2 chunks/iter, 2 CTA/SM, ~180 regs (255 cap) -----------
#define ASTR 40      // halfs per A smem row (32 + 8 pad) = 80B
#define BSTR 136     // halfs per B smem row (128 + 8 pad) = 272B
#define A_STAGE_B (128 * ASTR * 2)          // 10240
#define B_STAGE_B (32 * BSTR * 2)           // 8704
#define STAGE_B   (A_STAGE_B + B_STAGE_B)   // 18944
#define RING      5
#define SM_DYN    (RING * STAGE_B)          // 94720

template<int KTOT, int NTOT, bool FFN1>
__global__ __launch_bounds__(128, 2) void moe_gemm_kernel(
    const __half* __restrict__ Ain, const __half* __restrict__ W16,
    const float* __restrict__ Bias)
{
    const int NC = KTOT / 32;                // even for both GEMMs
    int e = blockIdx.z;
    int cnt = g_cnt[e];
    int rowbase = blockIdx.x * 128;
    if (rowbase >= cnt) return;
    int nbase = blockIdx.y * 128;
    int tid = threadIdx.x;
    int lane = tid & 31;
    int warp = tid >> 5;
    int wm = warp >> 1, wn = warp & 1;       // 2 x 2 warps, warp tile 64x64

    extern __shared__ char smdyn[];
    __shared__ int   dst_s[128];
    __shared__ float wt_s[128];
    __shared__ float bias_s[128];
    __shared__ int   src_s[128];

    {
        int r = rowbase + tid;
        int src = 0, dst = -1; float w = 0.f;
        if (r < cnt) {
            if (FFN1) { src = g_tok[e * T_TOK + r];  dst = g_slot[e * T_TOK + r]; }
            else      { src = g_slot[e * T_TOK + r]; dst = g_slot[e * T_TOK + r];
                        w = g_wt[e * T_TOK + r]; }
        }
        src_s[tid] = src; dst_s[tid] = dst; wt_s[tid] = w;
        bias_s[tid] = Bias[(size_t)e * NTOT + nbase + tid];
    }
    __syncthreads();

    uint32_t smb = smem_u32(smdyn);

    // A loader: thread tid owns row tid (32 halfs = 4 cp16)
    const __half* aP = Ain + (size_t)src_s[tid] * KTOT;
    uint32_t a_dst0 = (uint32_t)(tid * ASTR) * 2;
    // B loader: 4 threads/row, 32 rows; each 32 halfs = 4 cp16
    int brow = tid >> 2;
    int bcol = (tid & 3) * 32;
    const __half* bP = W16 + (size_t)e * KTOT * NTOT + (size_t)brow * NTOT + nbase + bcol;
    uint32_t b_dst0 = (uint32_t)(A_STAGE_B) + (uint32_t)(brow * BSTR + bcol) * 2;

    int lr = lane & 15, lc = lane >> 4;
    uint32_t a_ld0 = (uint32_t)((wm * 64 + lr) * ASTR + lc * 8) * 2;
    uint32_t b_ld0 = (uint32_t)(A_STAGE_B) + (uint32_t)(lr * BSTR + wn * 64 + lc * 8) * 2;

    float acc[4][8][4];
#pragma unroll
    for (int i = 0; i < 4; i++)
#pragma unroll
        for (int j = 0; j < 8; j++)
#pragma unroll
            for (int k = 0; k < 4; k++) acc[i][j][k] = 0.f;

    auto issue_chunk = [&](int ch) {
        uint32_t sb = smb + (uint32_t)(ch % RING) * STAGE_B;
        int k0 = ch * 32;
        const __half* ap = aP + k0;
#pragma unroll
        for (int j = 0; j < 4; j++)
            cp16(sb + a_dst0 + j * 16u, ap + j * 8);
        const __half* bp = bP + (size_t)k0 * NTOT;
#pragma unroll
        for (int j = 0; j < 4; j++)
            cp16(sb + b_dst0 + j * 16u, bp + j * 8);
        cp_commit();
    };

    issue_chunk(0);
    issue_chunk(1);
    issue_chunk(2);

#pragma unroll 1
    for (int c = 0; c < NC; c += 2) {
        cp_wait<1>();
        __syncthreads();
        if (c + 3 < NC) issue_chunk(c + 3); else cp_commit();
        if (c + 4 < NC) issue_chunk(c + 4); else cp_commit();
#pragma unroll
        for (int cc = 0; cc < 2; cc++) {
            uint32_t sb = smb + (uint32_t)((c + cc) % RING) * STAGE_B;
#pragma unroll
            for (int ks = 0; ks < 2; ks++) {
                uint32_t afr[4][4], bfr[4][4];
#pragma unroll
                for (int mf = 0; mf < 4; mf++)
                    ldsm_x4(afr[mf], sb + a_ld0 + (uint32_t)(mf * 16 * ASTR + ks * 16) * 2);
#pragma unroll
                for (int np = 0; np < 4; np++)
                    ldsm_x4_t(bfr[np], sb + b_ld0 + (uint32_t)(ks * 16 * BSTR + np * 16) * 2);
#pragma unroll
                for (int mf = 0; mf < 4; mf++)
#pragma unroll
                    for (int nf = 0; nf < 8; nf++)
                        mma16816(acc[mf][nf], afr[mf], &bfr[nf >> 1][(nf & 1) * 2]);
            }
        }
    }

    // ---- epilogue ----
    int crow = lane >> 2;
    int ccol = (lane & 3) * 2;
#pragma unroll
    for (int mf = 0; mf < 4; mf++) {
#pragma unroll
        for (int half_ = 0; half_ < 2; half_++) {
            int mloc = wm * 64 + mf * 16 + crow + half_ * 8;
            int dst = dst_s[mloc];
            if (dst < 0) continue;
            float wv = wt_s[mloc];
#pragma unroll
            for (int nf = 0; nf < 8; nf++) {
                int nloc = wn * 64 + nf * 8 + ccol;
                float v0 = acc[mf][nf][half_ * 2 + 0] + bias_s[nloc];
                float v1 = acc[mf][nf][half_ * 2 + 1] + bias_s[nloc + 1];
                if (FFN1) {
                    v0 = 0.5f * v0 * (1.0f + erff(v0 * 0.70710678118654752f));
                    v1 = 0.5f * v1 * (1.0f + erff(v1 * 0.70710678118654752f));
                    __half2 h = __floats2half2_rn(v0, v1);
                    *(__half2*)(g_mid + (size_t)dst * NTOT + nbase + nloc) = h;
                } else {
                    float2 o = make_float2(wv * v0, wv * v1);
                    *(float2*)(g_out2 + (size_t)dst * NTOT + nbase + nloc) = o;
                }
            }
        }
    }
}

// ---------------------------------------------------------------------------
extern "C" void kernel_launch(void* const* d_in, const int* in_sizes, int n_in,
                              void* d_out, int out_size) {
    const float* x      = (const float*)d_in[0];
    const float* gate_w = (const float*)d_in[1];
    const float* gate_b = (const float*)d_in[2];
    const float* w1     = (const float*)d_in[3];
    const float* b1     = (const float*)d_in[4];
    const float* w2     = (const float*)d_in[5];
    const float* b2     = (const float*)d_in[6];
    float* out    = (float*)d_out;
    float* logits = (float*)d_out + OUT_ELEMS;
    (void)in_sizes; (void)n_in; (void)out_size;

    __half *px, *pmid, *pw1, *pw2;
    cudaGetSymbolAddress((void**)&px,   g_x16);
    cudaGetSymbolAddress((void**)&pmid, g_mid);
    cudaGetSymbolAddress((void**)&pw1,  g_w1h);
    cudaGetSymbolAddress((void**)&pw2,  g_w2h);

    cudaFuncSetAttribute(moe_gemm_kernel<D_DIM, H_DIM, true>,
                         cudaFuncAttributeMaxDynamicSharedMemorySize, SM_DYN);
    cudaFuncSetAttribute(moe_gemm_kernel<H_DIM, D_DIM, false>,
                         cudaFuncAttributeMaxDynamicSharedMemorySize, SM_DYN);

    preamble_kernel<<<PRE_GRID, 256>>>(x, gate_w, gate_b, logits,
                                       (const float4*)w1, (const float4*)w2);

    dim3 g1(T_TOK / 128, H_DIM / 128, E_NUM);   // (64, 32, 8)
    moe_gemm_kernel<D_DIM, H_DIM, true><<<g1, 128, SM_DYN>>>(px, pw1, b1);

    dim3 g2(T_TOK / 128, D_DIM / 128, E_NUM);   // (64, 8, 8)
    moe_gemm_kernel<H_DIM, D_DIM, false><<<g2, 128, SM_DYN>>>(pmid, pw2, b2);

    combine_kernel<<<(OUT_ELEMS / 4 + 255) / 256, 256>>>((float4*)out);
}